// round 6
// baseline (speedup 1.0000x reference)
#include <cuda_runtime.h>
#include <math.h>

#define B_ 64
#define S_ 64
#define T_ 64
#define H_ 1024
#define E_ 1024
#define G_ 3072        // 3*H
#define V_ 32000
#define KC 32          // K-chunk for gru gemm passes

// ---------------- scratch (device globals; no runtime allocation) -------------
__device__ float g_gi0[S_ * B_ * G_];          // precomputed gi for layer 0, [step][b][3H] (48 MB, reused enc->dec)
__device__ float g_h[2][2][B_ * H_];           // hidden state [layer][parity][b*H+j]
__device__ float g_xl[B_ * H_];                // layer-0 output (input to layer 1) for current step
__device__ float g_top[(T_ - 1) * B_ * H_];    // decoder top-layer outputs, [s][b][H]

__device__ __forceinline__ float sigm(float x) { return 1.0f / (1.0f + expf(-x)); }

// ---------------- init: zero h(parity 0) and out[:,0,:] -----------------------
__global__ void init_kernel(float* __restrict__ out) {
    const int idx = blockIdx.x * blockDim.x + threadIdx.x;
    const int stride = gridDim.x * blockDim.x;
    if (idx < B_ * H_) {
        g_h[0][0][idx] = 0.0f;
        g_h[1][0][idx] = 0.0f;
    }
    for (int i = idx; i < B_ * V_; i += stride) {
        const int b = i / V_;
        const int v = i - b * V_;
        out[(size_t)b * (T_ * V_) + v] = 0.0f;   // outputs[:,0,:] = 0
    }
}

// ---------------- layer-0 input projection (embedding gather GEMM) ------------
// g_gi0[t*B+b, n] = sum_k emb[tok[b,t], k] * W[n, k] + bias[n]
// grid: (G_/64, nsteps), block: 256. Tile 64 rows (all b) x 64 cols.
__global__ void __launch_bounds__(256) gi0_kernel(
    const int* __restrict__ tokens, int tok_ld,
    const float* __restrict__ emb,
    const float* __restrict__ W,
    const float* __restrict__ bias)
{
    __shared__ __align__(16) float As[16][68];
    __shared__ __align__(16) float Ws[16][68];
    __shared__ int toks[64];

    const int t   = blockIdx.y;
    const int n0  = blockIdx.x * 64;
    const int tid = threadIdx.x;

    if (tid < 64) toks[tid] = tokens[tid * tok_ld + t];   // tokens[b][t]
    __syncthreads();

    float acc[4][4];
#pragma unroll
    for (int i = 0; i < 4; i++)
#pragma unroll
        for (int j = 0; j < 4; j++) acc[i][j] = 0.0f;

    const int lr = tid >> 2;          // 0..63 (loader row)
    const int lk = (tid & 3) << 2;    // 0,4,8,12 (loader k offset)
    const int ty = tid >> 4;          // 0..15 (row group of 4)
    const int tx = tid & 15;          // 0..15 (col group of 4)

    const float* arow = emb + (size_t)toks[lr] * E_ + lk;
    const float* wrow = W + (size_t)(n0 + lr) * E_ + lk;

    for (int k0 = 0; k0 < E_; k0 += 16) {
        const float4 a = *(const float4*)(arow + k0);
        const float4 w = *(const float4*)(wrow + k0);
        As[lk + 0][lr] = a.x; As[lk + 1][lr] = a.y; As[lk + 2][lr] = a.z; As[lk + 3][lr] = a.w;
        Ws[lk + 0][lr] = w.x; Ws[lk + 1][lr] = w.y; Ws[lk + 2][lr] = w.z; Ws[lk + 3][lr] = w.w;
        __syncthreads();
#pragma unroll
        for (int kk = 0; kk < 16; kk++) {
            const float4 av = *(const float4*)&As[kk][ty << 2];
            const float4 wv = *(const float4*)&Ws[kk][tx << 2];
            acc[0][0] += av.x * wv.x; acc[0][1] += av.x * wv.y; acc[0][2] += av.x * wv.z; acc[0][3] += av.x * wv.w;
            acc[1][0] += av.y * wv.x; acc[1][1] += av.y * wv.y; acc[1][2] += av.y * wv.z; acc[1][3] += av.y * wv.w;
            acc[2][0] += av.z * wv.x; acc[2][1] += av.z * wv.y; acc[2][2] += av.z * wv.z; acc[2][3] += av.z * wv.w;
            acc[3][0] += av.w * wv.x; acc[3][1] += av.w * wv.y; acc[3][2] += av.w * wv.z; acc[3][3] += av.w * wv.w;
        }
        __syncthreads();
    }

#pragma unroll
    for (int i = 0; i < 4; i++) {
        const int b = (ty << 2) + i;
        float* dst = g_gi0 + ((size_t)t * B_ + b) * G_ + n0 + (tx << 2);
#pragma unroll
        for (int j = 0; j < 4; j++)
            dst[j] = acc[i][j] + bias[n0 + (tx << 2) + j];
    }
}

// ---------------- recurrent gemm pass: acc[gate][row] += A(64x1024) @ W rows ---
// CTA owns 8 hidden columns j0..j0+7 -> W rows {gate*H + j0 + cj}.
// block: 128 threads: cj = tid&7 (hidden col), rb = tid>>3 (4-row block).
__device__ __forceinline__ void gru_gemm_pass(
    const float* __restrict__ A,
    const float* __restrict__ W,
    int j0, float (&acc)[3][4],
    float (*As)[68], float (*Ws)[25])
{
    const int tid = threadIdx.x;
    const int cj  = tid & 7;
    const int rb  = tid >> 3;

    for (int k0 = 0; k0 < H_; k0 += KC) {
        // load A chunk 64x32 (512 float4, 4 per thread), transposed into As[k][r]
#pragma unroll
        for (int i = 0; i < 4; i++) {
            const int lin = tid + i * 128;
            const int r   = lin >> 3;
            const int kk  = (lin & 7) << 2;
            const float4 v = *(const float4*)(A + (size_t)r * H_ + k0 + kk);
            As[kk + 0][r] = v.x; As[kk + 1][r] = v.y; As[kk + 2][r] = v.z; As[kk + 3][r] = v.w;
        }
        // load W chunk: 24 rows x 32 k (192 float4)
        {
            int lin = tid;
            int g = lin >> 3, kk = (lin & 7) << 2;
            const float* src = W + ((size_t)(g >> 3) * H_ + j0 + (g & 7)) * H_ + k0 + kk;
            float4 v = *(const float4*)src;
            Ws[kk + 0][g] = v.x; Ws[kk + 1][g] = v.y; Ws[kk + 2][g] = v.z; Ws[kk + 3][g] = v.w;
            if (tid < 64) {
                lin = tid + 128;
                g = lin >> 3; kk = (lin & 7) << 2;
                src = W + ((size_t)(g >> 3) * H_ + j0 + (g & 7)) * H_ + k0 + kk;
                v = *(const float4*)src;
                Ws[kk + 0][g] = v.x; Ws[kk + 1][g] = v.y; Ws[kk + 2][g] = v.z; Ws[kk + 3][g] = v.w;
            }
        }
        __syncthreads();
#pragma unroll
        for (int kk = 0; kk < KC; kk++) {
            const float4 av = *(const float4*)&As[kk][rb << 2];
            const float wr = Ws[kk][cj];
            const float wz = Ws[kk][8 + cj];
            const float wn = Ws[kk][16 + cj];
            acc[0][0] += av.x * wr; acc[0][1] += av.y * wr; acc[0][2] += av.z * wr; acc[0][3] += av.w * wr;
            acc[1][0] += av.x * wz; acc[1][1] += av.y * wz; acc[1][2] += av.z * wz; acc[1][3] += av.w * wz;
            acc[2][0] += av.x * wn; acc[2][1] += av.y * wn; acc[2][2] += av.z * wn; acc[2][3] += av.w * wn;
        }
        __syncthreads();
    }
}

// ---------------- layer-0 step: gh = h0 @ Whh0^T, gi precomputed --------------
// grid: 128 CTAs (8 hidden cols each), block: 128
__global__ void __launch_bounds__(128) gru_l0_kernel(
    const float* __restrict__ Whh, const float* __restrict__ bhh,
    const int* __restrict__ lengths, int t, int parity)
{
    __shared__ __align__(16) float As[KC][68];
    __shared__ float Ws[KC][25];

    const int j0  = blockIdx.x * 8;
    const int tid = threadIdx.x;
    const int cj  = tid & 7;
    const int rb  = tid >> 3;

    const float* hread = g_h[0][parity];
    float acc[3][4];
#pragma unroll
    for (int g = 0; g < 3; g++)
#pragma unroll
        for (int i = 0; i < 4; i++) acc[g][i] = 0.0f;

    gru_gemm_pass(hread, Whh, j0, acc, As, Ws);

    const int j = j0 + cj;
    const float* gi = g_gi0 + (size_t)t * B_ * G_;
    float* hwrite = g_h[0][parity ^ 1];
    const float br = bhh[j], bz = bhh[H_ + j], bn = bhh[2 * H_ + j];

#pragma unroll
    for (int i = 0; i < 4; i++) {
        const int b = (rb << 2) + i;
        const float hprev = hread[b * H_ + j];
        const float gir = gi[(size_t)b * G_ + j];
        const float giz = gi[(size_t)b * G_ + H_ + j];
        const float gin = gi[(size_t)b * G_ + 2 * H_ + j];
        const float r = sigm(gir + acc[0][i] + br);
        const float z = sigm(giz + acc[1][i] + bz);
        const float n = tanhf(gin + r * (acc[2][i] + bn));
        const float hnew = (1.0f - z) * n + z * hprev;
        g_xl[b * H_ + j] = hnew;                       // layer-1 input (unmasked)
        float hs = hnew;
        if (lengths != nullptr && t >= lengths[b]) hs = hprev;   // packed-seq freeze
        hwrite[b * H_ + j] = hs;
    }
}

// ---------------- layer-1 step: gi = xl @ Wih1^T, gh = h1 @ Whh1^T ------------
__global__ void __launch_bounds__(128) gru_l1_kernel(
    const float* __restrict__ Wih, const float* __restrict__ Whh,
    const float* __restrict__ bih, const float* __restrict__ bhh,
    const int* __restrict__ lengths, int t, int parity, int store_top)
{
    __shared__ __align__(16) float As[KC][68];
    __shared__ float Ws[KC][25];

    const int j0  = blockIdx.x * 8;
    const int tid = threadIdx.x;
    const int cj  = tid & 7;
    const int rb  = tid >> 3;

    const float* hread = g_h[1][parity];

    float gia[3][4], gha[3][4];
#pragma unroll
    for (int g = 0; g < 3; g++)
#pragma unroll
        for (int i = 0; i < 4; i++) { gia[g][i] = 0.0f; gha[g][i] = 0.0f; }

    gru_gemm_pass(g_xl,  Wih, j0, gia, As, Ws);
    gru_gemm_pass(hread, Whh, j0, gha, As, Ws);

    const int j = j0 + cj;
    float* hwrite = g_h[1][parity ^ 1];
    const float bir = bih[j], biz = bih[H_ + j], bin = bih[2 * H_ + j];
    const float bhr = bhh[j], bhz = bhh[H_ + j], bhn = bhh[2 * H_ + j];

#pragma unroll
    for (int i = 0; i < 4; i++) {
        const int b = (rb << 2) + i;
        const float hprev = hread[b * H_ + j];
        const float r = sigm((gia[0][i] + bir) + (gha[0][i] + bhr));
        const float z = sigm((gia[1][i] + biz) + (gha[1][i] + bhz));
        const float n = tanhf((gia[2][i] + bin) + r * (gha[2][i] + bhn));
        const float hnew = (1.0f - z) * n + z * hprev;
        if (store_top) g_top[((size_t)t * B_ + b) * H_ + j] = hnew;
        float hs = hnew;
        if (lengths != nullptr && t >= lengths[b]) hs = hprev;
        hwrite[b * H_ + j] = hs;
    }
}

// ---------------- output GEMM: out[b, s+1, v] = g_top[s,b,:] @ Wout[v,:] + bout
// grid: (V_/64, T_-1), block: 256
__global__ void __launch_bounds__(256) out_gemm_kernel(
    const float* __restrict__ W, const float* __restrict__ bias,
    float* __restrict__ out)
{
    __shared__ __align__(16) float As[16][68];
    __shared__ __align__(16) float Ws[16][68];

    const int s   = blockIdx.y;
    const int n0  = blockIdx.x * 64;
    const int tid = threadIdx.x;

    float acc[4][4];
#pragma unroll
    for (int i = 0; i < 4; i++)
#pragma unroll
        for (int j = 0; j < 4; j++) acc[i][j] = 0.0f;

    const int lr = tid >> 2;
    const int lk = (tid & 3) << 2;
    const int ty = tid >> 4;
    const int tx = tid & 15;

    const float* arow = g_top + ((size_t)s * B_ + lr) * H_ + lk;
    const float* wrow = W + (size_t)(n0 + lr) * H_ + lk;

    for (int k0 = 0; k0 < H_; k0 += 16) {
        const float4 a = *(const float4*)(arow + k0);
        const float4 w = *(const float4*)(wrow + k0);
        As[lk + 0][lr] = a.x; As[lk + 1][lr] = a.y; As[lk + 2][lr] = a.z; As[lk + 3][lr] = a.w;
        Ws[lk + 0][lr] = w.x; Ws[lk + 1][lr] = w.y; Ws[lk + 2][lr] = w.z; Ws[lk + 3][lr] = w.w;
        __syncthreads();
#pragma unroll
        for (int kk = 0; kk < 16; kk++) {
            const float4 av = *(const float4*)&As[kk][ty << 2];
            const float4 wv = *(const float4*)&Ws[kk][tx << 2];
            acc[0][0] += av.x * wv.x; acc[0][1] += av.x * wv.y; acc[0][2] += av.x * wv.z; acc[0][3] += av.x * wv.w;
            acc[1][0] += av.y * wv.x; acc[1][1] += av.y * wv.y; acc[1][2] += av.y * wv.z; acc[1][3] += av.y * wv.w;
            acc[2][0] += av.z * wv.x; acc[2][1] += av.z * wv.y; acc[2][2] += av.z * wv.z; acc[2][3] += av.z * wv.w;
            acc[3][0] += av.w * wv.x; acc[3][1] += av.w * wv.y; acc[3][2] += av.w * wv.z; acc[3][3] += av.w * wv.w;
        }
        __syncthreads();
    }

#pragma unroll
    for (int i = 0; i < 4; i++) {
        const int b = (ty << 2) + i;
        float* dst = out + (size_t)b * (T_ * V_) + (size_t)(s + 1) * V_ + n0 + (tx << 2);
#pragma unroll
        for (int j = 0; j < 4; j++)
            dst[j] = acc[i][j] + bias[n0 + (tx << 2) + j];
    }
}

// ------------------------------- host driver ----------------------------------
extern "C" void kernel_launch(void* const* d_in, const int* in_sizes, int n_in,
                              void* d_out, int out_size) {
    (void)in_sizes; (void)n_in; (void)out_size;

    const int*   src_tokens  = (const int*)d_in[0];
    const int*   src_lengths = (const int*)d_in[1];
    const int*   trg         = (const int*)d_in[2];
    const float* emb_enc = (const float*)d_in[3];
    const float* Wih_enc = (const float*)d_in[4];
    const float* Whh_enc = (const float*)d_in[5];
    const float* bih_enc = (const float*)d_in[6];
    const float* bhh_enc = (const float*)d_in[7];
    const float* emb_dec = (const float*)d_in[8];
    const float* Wih_dec = (const float*)d_in[9];
    const float* Whh_dec = (const float*)d_in[10];
    const float* bih_dec = (const float*)d_in[11];
    const float* bhh_dec = (const float*)d_in[12];
    const float* Wout    = (const float*)d_in[13];
    const float* bout    = (const float*)d_in[14];
    float* out = (float*)d_out;

    const size_t LW = (size_t)G_ * H_;   // per-layer weight stride (3H x 1024)
    const size_t LB = (size_t)G_;        // per-layer bias stride

    // 1) init: zero h state (parity 0) + zero out[:,0,:]
    init_kernel<<<512, 256>>>(out);

    // 2) encoder layer-0 input projection for all S steps
    gi0_kernel<<<dim3(G_ / 64, S_), 256>>>(src_tokens, S_, emb_enc, Wih_enc, bih_enc);

    // 3) encoder recurrence
    for (int t = 0; t < S_; t++) {
        const int p = t & 1;
        gru_l0_kernel<<<H_ / 8, 128>>>(Whh_enc, bhh_enc, src_lengths, t, p);
        gru_l1_kernel<<<H_ / 8, 128>>>(Wih_enc + LW, Whh_enc + LW,
                                       bih_enc + LB, bhh_enc + LB,
                                       src_lengths, t, p, 0);
    }

    // 4) decoder layer-0 input projection (tokens trg[:, 0..T-2])
    gi0_kernel<<<dim3(G_ / 64, T_ - 1), 256>>>(trg, T_, emb_dec, Wih_dec, bih_dec);

    // 5) decoder recurrence (continues parity: encoder ran S_=64 steps, even)
    for (int s = 0; s < T_ - 1; s++) {
        const int p = s & 1;
        gru_l0_kernel<<<H_ / 8, 128>>>(Whh_dec, bhh_dec, nullptr, s, p);
        gru_l1_kernel<<<H_ / 8, 128>>>(Wih_dec + LW, Whh_dec + LW,
                                       bih_dec + LB, bhh_dec + LB,
                                       nullptr, s, p, 1);
    }

    // 6) vocab projection for all steps at once
    out_gemm_kernel<<<dim3(V_ / 64, T_ - 1), 256>>>(Wout, bout, out);
}

// round 8
// speedup vs baseline: 1.0459x; 1.0459x over previous
#include <cuda_runtime.h>
#include <math.h>

#define B_ 64
#define S_ 64
#define T_ 64
#define H_ 1024
#define E_ 1024
#define G_ 3072        // 3*H
#define V_ 32000
#define KC 32          // K-chunk for gru gemm passes

// ---------------- scratch (device globals; no runtime allocation) -------------
__device__ float g_gi0[S_ * B_ * G_];          // precomputed gi for layer 0, [step][b][3H] (48 MB, reused enc->dec)
__device__ float g_h[2][2][B_ * H_];           // hidden state [layer][parity][b*H+j]
__device__ float g_xl[B_ * H_];                // layer-0 output (input to layer 1) for current step
__device__ float g_top[(T_ - 1) * B_ * H_];    // decoder top-layer outputs, [s][b][H]

__device__ __forceinline__ float sigm(float x) { return 1.0f / (1.0f + expf(-x)); }

// ---------------- init: zero h(parity 0) and out[:,0,:] -----------------------
__global__ void init_kernel(float* __restrict__ out) {
    const int idx = blockIdx.x * blockDim.x + threadIdx.x;
    const int stride = gridDim.x * blockDim.x;
    if (idx < B_ * H_) {
        g_h[0][0][idx] = 0.0f;
        g_h[1][0][idx] = 0.0f;
    }
    for (int i = idx; i < B_ * V_; i += stride) {
        const int b = i / V_;
        const int v = i - b * V_;
        out[(size_t)b * (T_ * V_) + v] = 0.0f;   // outputs[:,0,:] = 0
    }
}

// ---------------- layer-0 input projection (embedding gather GEMM) ------------
// g_gi0[t*B+b, n] = sum_k emb[tok[b,t], k] * W[n, k] + bias[n]
// grid: (G_/64, nsteps), block: 256. Tile 64 rows (all b) x 64 cols.
__global__ void __launch_bounds__(256) gi0_kernel(
    const int* __restrict__ tokens, int tok_ld,
    const float* __restrict__ emb,
    const float* __restrict__ W,
    const float* __restrict__ bias)
{
    __shared__ __align__(16) float As[16][68];
    __shared__ __align__(16) float Ws[16][68];
    __shared__ int toks[64];

    const int t   = blockIdx.y;
    const int n0  = blockIdx.x * 64;
    const int tid = threadIdx.x;

    if (tid < 64) toks[tid] = tokens[tid * tok_ld + t];   // tokens[b][t]
    __syncthreads();

    float acc[4][4];
#pragma unroll
    for (int i = 0; i < 4; i++)
#pragma unroll
        for (int j = 0; j < 4; j++) acc[i][j] = 0.0f;

    const int lr = tid >> 2;          // 0..63 (loader row)
    const int lk = (tid & 3) << 2;    // 0,4,8,12 (loader k offset)
    const int ty = tid >> 4;          // 0..15 (row group of 4)
    const int tx = tid & 15;          // 0..15 (col group of 4)

    const float* arow = emb + (size_t)toks[lr] * E_ + lk;
    const float* wrow = W + (size_t)(n0 + lr) * E_ + lk;

    for (int k0 = 0; k0 < E_; k0 += 16) {
        const float4 a = *(const float4*)(arow + k0);
        const float4 w = *(const float4*)(wrow + k0);
        As[lk + 0][lr] = a.x; As[lk + 1][lr] = a.y; As[lk + 2][lr] = a.z; As[lk + 3][lr] = a.w;
        Ws[lk + 0][lr] = w.x; Ws[lk + 1][lr] = w.y; Ws[lk + 2][lr] = w.z; Ws[lk + 3][lr] = w.w;
        __syncthreads();
#pragma unroll
        for (int kk = 0; kk < 16; kk++) {
            const float4 av = *(const float4*)&As[kk][ty << 2];
            const float4 wv = *(const float4*)&Ws[kk][tx << 2];
            acc[0][0] += av.x * wv.x; acc[0][1] += av.x * wv.y; acc[0][2] += av.x * wv.z; acc[0][3] += av.x * wv.w;
            acc[1][0] += av.y * wv.x; acc[1][1] += av.y * wv.y; acc[1][2] += av.y * wv.z; acc[1][3] += av.y * wv.w;
            acc[2][0] += av.z * wv.x; acc[2][1] += av.z * wv.y; acc[2][2] += av.z * wv.z; acc[2][3] += av.z * wv.w;
            acc[3][0] += av.w * wv.x; acc[3][1] += av.w * wv.y; acc[3][2] += av.w * wv.z; acc[3][3] += av.w * wv.w;
        }
        __syncthreads();
    }

#pragma unroll
    for (int i = 0; i < 4; i++) {
        const int b = (ty << 2) + i;
        float* dst = g_gi0 + ((size_t)t * B_ + b) * G_ + n0 + (tx << 2);
#pragma unroll
        for (int j = 0; j < 4; j++)
            dst[j] = acc[i][j] + bias[n0 + (tx << 2) + j];
    }
}

// ---------------- recurrent gemm pass: acc[gate][row] += A(64x1024) @ W rows ---
// CTA owns 8 hidden columns j0..j0+7 -> W rows {gate*H + j0 + cj}.
// block: 128 threads: cj = tid&7 (hidden col), rb = tid>>3 (4-row block).
__device__ __forceinline__ void gru_gemm_pass(
    const float* __restrict__ A,
    const float* __restrict__ W,
    int j0, float (&acc)[3][4],
    float (*As)[68], float (*Ws)[25])
{
    const int tid = threadIdx.x;
    const int cj  = tid & 7;
    const int rb  = tid >> 3;

    for (int k0 = 0; k0 < H_; k0 += KC) {
        // load A chunk 64x32 (512 float4, 4 per thread), transposed into As[k][r]
#pragma unroll
        for (int i = 0; i < 4; i++) {
            const int lin = tid + i * 128;
            const int r   = lin >> 3;
            const int kk  = (lin & 7) << 2;
            const float4 v = *(const float4*)(A + (size_t)r * H_ + k0 + kk);
            As[kk + 0][r] = v.x; As[kk + 1][r] = v.y; As[kk + 2][r] = v.z; As[kk + 3][r] = v.w;
        }
        // load W chunk: 24 rows x 32 k (192 float4)
        {
            int lin = tid;
            int g = lin >> 3, kk = (lin & 7) << 2;
            const float* src = W + ((size_t)(g >> 3) * H_ + j0 + (g & 7)) * H_ + k0 + kk;
            float4 v = *(const float4*)src;
            Ws[kk + 0][g] = v.x; Ws[kk + 1][g] = v.y; Ws[kk + 2][g] = v.z; Ws[kk + 3][g] = v.w;
            if (tid < 64) {
                lin = tid + 128;
                g = lin >> 3; kk = (lin & 7) << 2;
                src = W + ((size_t)(g >> 3) * H_ + j0 + (g & 7)) * H_ + k0 + kk;
                v = *(const float4*)src;
                Ws[kk + 0][g] = v.x; Ws[kk + 1][g] = v.y; Ws[kk + 2][g] = v.z; Ws[kk + 3][g] = v.w;
            }
        }
        __syncthreads();
#pragma unroll
        for (int kk = 0; kk < KC; kk++) {
            const float4 av = *(const float4*)&As[kk][rb << 2];
            const float wr = Ws[kk][cj];
            const float wz = Ws[kk][8 + cj];
            const float wn = Ws[kk][16 + cj];
            acc[0][0] += av.x * wr; acc[0][1] += av.y * wr; acc[0][2] += av.z * wr; acc[0][3] += av.w * wr;
            acc[1][0] += av.x * wz; acc[1][1] += av.y * wz; acc[1][2] += av.z * wz; acc[1][3] += av.w * wz;
            acc[2][0] += av.x * wn; acc[2][1] += av.y * wn; acc[2][2] += av.z * wn; acc[2][3] += av.w * wn;
        }
        __syncthreads();
    }
}

// ---------------- layer-0 step: gh = h0 @ Whh0^T, gi precomputed --------------
// grid: 128 CTAs (8 hidden cols each), block: 128
__global__ void __launch_bounds__(128) gru_l0_kernel(
    const float* __restrict__ Whh, const float* __restrict__ bhh,
    const int* __restrict__ lengths, int t, int parity)
{
    __shared__ __align__(16) float As[KC][68];
    __shared__ float Ws[KC][25];

    const int j0  = blockIdx.x * 8;
    const int tid = threadIdx.x;
    const int cj  = tid & 7;
    const int rb  = tid >> 3;

    const float* hread = g_h[0][parity];
    float acc[3][4];
#pragma unroll
    for (int g = 0; g < 3; g++)
#pragma unroll
        for (int i = 0; i < 4; i++) acc[g][i] = 0.0f;

    gru_gemm_pass(hread, Whh, j0, acc, As, Ws);

    const int j = j0 + cj;
    const float* gi = g_gi0 + (size_t)t * B_ * G_;
    float* hwrite = g_h[0][parity ^ 1];
    const float br = bhh[j], bz = bhh[H_ + j], bn = bhh[2 * H_ + j];

#pragma unroll
    for (int i = 0; i < 4; i++) {
        const int b = (rb << 2) + i;
        const float hprev = hread[b * H_ + j];
        const float gir = gi[(size_t)b * G_ + j];
        const float giz = gi[(size_t)b * G_ + H_ + j];
        const float gin = gi[(size_t)b * G_ + 2 * H_ + j];
        const float r = sigm(gir + acc[0][i] + br);
        const float z = sigm(giz + acc[1][i] + bz);
        const float n = tanhf(gin + r * (acc[2][i] + bn));
        const float hnew = (1.0f - z) * n + z * hprev;
        g_xl[b * H_ + j] = hnew;                       // layer-1 input (unmasked)
        float hs = hnew;
        if (lengths != nullptr && t >= lengths[b]) hs = hprev;   // packed-seq freeze
        hwrite[b * H_ + j] = hs;
    }
}

// ---------------- layer-1 step: gi = xl @ Wih1^T, gh = h1 @ Whh1^T ------------
__global__ void __launch_bounds__(128) gru_l1_kernel(
    const float* __restrict__ Wih, const float* __restrict__ Whh,
    const float* __restrict__ bih, const float* __restrict__ bhh,
    const int* __restrict__ lengths, int t, int parity, int store_top)
{
    __shared__ __align__(16) float As[KC][68];
    __shared__ float Ws[KC][25];

    const int j0  = blockIdx.x * 8;
    const int tid = threadIdx.x;
    const int cj  = tid & 7;
    const int rb  = tid >> 3;

    const float* hread = g_h[1][parity];

    float gia[3][4], gha[3][4];
#pragma unroll
    for (int g = 0; g < 3; g++)
#pragma unroll
        for (int i = 0; i < 4; i++) { gia[g][i] = 0.0f; gha[g][i] = 0.0f; }

    gru_gemm_pass(g_xl,  Wih, j0, gia, As, Ws);
    gru_gemm_pass(hread, Whh, j0, gha, As, Ws);

    const int j = j0 + cj;
    float* hwrite = g_h[1][parity ^ 1];
    const float bir = bih[j], biz = bih[H_ + j], bin = bih[2 * H_ + j];
    const float bhr = bhh[j], bhz = bhh[H_ + j], bhn = bhh[2 * H_ + j];

#pragma unroll
    for (int i = 0; i < 4; i++) {
        const int b = (rb << 2) + i;
        const float hprev = hread[b * H_ + j];
        const float r = sigm((gia[0][i] + bir) + (gha[0][i] + bhr));
        const float z = sigm((gia[1][i] + biz) + (gha[1][i] + bhz));
        const float n = tanhf((gia[2][i] + bin) + r * (gha[2][i] + bhn));
        const float hnew = (1.0f - z) * n + z * hprev;
        if (store_top) g_top[((size_t)t * B_ + b) * H_ + j] = hnew;
        float hs = hnew;
        if (lengths != nullptr && t >= lengths[b]) hs = hprev;
        hwrite[b * H_ + j] = hs;
    }
}

// ---------------- output GEMM: out[b, s+1, v] = g_top[s,b,:] @ Wout[v,:] + bout
// grid: (V_/64, T_-1), block: 256
__global__ void __launch_bounds__(256) out_gemm_kernel(
    const float* __restrict__ W, const float* __restrict__ bias,
    float* __restrict__ out)
{
    __shared__ __align__(16) float As[16][68];
    __shared__ __align__(16) float Ws[16][68];

    const int s   = blockIdx.y;
    const int n0  = blockIdx.x * 64;
    const int tid = threadIdx.x;

    float acc[4][4];
#pragma unroll
    for (int i = 0; i < 4; i++)
#pragma unroll
        for (int j = 0; j < 4; j++) acc[i][j] = 0.0f;

    const int lr = tid >> 2;
    const int lk = (tid & 3) << 2;
    const int ty = tid >> 4;
    const int tx = tid & 15;

    const float* arow = g_top + ((size_t)s * B_ + lr) * H_ + lk;
    const float* wrow = W + (size_t)(n0 + lr) * H_ + lk;

    for (int k0 = 0; k0 < H_; k0 += 16) {
        const float4 a = *(const float4*)(arow + k0);
        const float4 w = *(const float4*)(wrow + k0);
        As[lk + 0][lr] = a.x; As[lk + 1][lr] = a.y; As[lk + 2][lr] = a.z; As[lk + 3][lr] = a.w;
        Ws[lk + 0][lr] = w.x; Ws[lk + 1][lr] = w.y; Ws[lk + 2][lr] = w.z; Ws[lk + 3][lr] = w.w;
        __syncthreads();
#pragma unroll
        for (int kk = 0; kk < 16; kk++) {
            const float4 av = *(const float4*)&As[kk][ty << 2];
            const float4 wv = *(const float4*)&Ws[kk][tx << 2];
            acc[0][0] += av.x * wv.x; acc[0][1] += av.x * wv.y; acc[0][2] += av.x * wv.z; acc[0][3] += av.x * wv.w;
            acc[1][0] += av.y * wv.x; acc[1][1] += av.y * wv.y; acc[1][2] += av.y * wv.z; acc[1][3] += av.y * wv.w;
            acc[2][0] += av.z * wv.x; acc[2][1] += av.z * wv.y; acc[2][2] += av.z * wv.z; acc[2][3] += av.z * wv.w;
            acc[3][0] += av.w * wv.x; acc[3][1] += av.w * wv.y; acc[3][2] += av.w * wv.z; acc[3][3] += av.w * wv.w;
        }
        __syncthreads();
    }

#pragma unroll
    for (int i = 0; i < 4; i++) {
        const int b = (ty << 2) + i;
        float* dst = out + (size_t)b * (T_ * V_) + (size_t)(s + 1) * V_ + n0 + (tx << 2);
#pragma unroll
        for (int j = 0; j < 4; j++)
            dst[j] = acc[i][j] + bias[n0 + (tx << 2) + j];
    }
}

// ------------------------------- host driver ----------------------------------
extern "C" void kernel_launch(void* const* d_in, const int* in_sizes, int n_in,
                              void* d_out, int out_size) {
    (void)in_sizes; (void)n_in; (void)out_size;

    const int*   src_tokens  = (const int*)d_in[0];
    const int*   src_lengths = (const int*)d_in[1];
    const int*   trg         = (const int*)d_in[2];
    const float* emb_enc = (const float*)d_in[3];
    const float* Wih_enc = (const float*)d_in[4];
    const float* Whh_enc = (const float*)d_in[5];
    const float* bih_enc = (const float*)d_in[6];
    const float* bhh_enc = (const float*)d_in[7];
    const float* emb_dec = (const float*)d_in[8];
    const float* Wih_dec = (const float*)d_in[9];
    const float* Whh_dec = (const float*)d_in[10];
    const float* bih_dec = (const float*)d_in[11];
    const float* bhh_dec = (const float*)d_in[12];
    const float* Wout    = (const float*)d_in[13];
    const float* bout    = (const float*)d_in[14];
    float* out = (float*)d_out;

    const size_t LW = (size_t)G_ * H_;   // per-layer weight stride (3H x 1024)
    const size_t LB = (size_t)G_;        // per-layer bias stride

    // 1) init: zero h state (parity 0) + zero out[:,0,:]
    init_kernel<<<512, 256>>>(out);

    // 2) encoder layer-0 input projection for all S steps
    gi0_kernel<<<dim3(G_ / 64, S_), 256>>>(src_tokens, S_, emb_enc, Wih_enc, bih_enc);

    // 3) encoder recurrence
    for (int t = 0; t < S_; t++) {
        const int p = t & 1;
        gru_l0_kernel<<<H_ / 8, 128>>>(Whh_enc, bhh_enc, src_lengths, t, p);
        gru_l1_kernel<<<H_ / 8, 128>>>(Wih_enc + LW, Whh_enc + LW,
                                       bih_enc + LB, bhh_enc + LB,
                                       src_lengths, t, p, 0);
    }

    // 4) decoder layer-0 input projection (tokens trg[:, 0..T-2])
    gi0_kernel<<<dim3(G_ / 64, T_ - 1), 256>>>(trg, T_, emb_dec, Wih_dec, bih_dec);

    // 5) decoder recurrence (continues parity: encoder ran S_=64 steps, even)
    for (int s = 0; s < T_ - 1; s++) {
        const int p = s & 1;
        gru_l0_kernel<<<H_ / 8, 128>>>(Whh_dec, bhh_dec, nullptr, s, p);
        gru_l1_kernel<<<H_ / 8, 128>>>(Wih_dec + LW, Whh_dec + LW,
                                       bih_dec + LB, bhh_dec + LB,
                                       nullptr, s, p, 1);
    }

    // 6) vocab projection for all steps at once
    out_gemm_kernel<<<dim3(V_ / 64, T_ - 1), 256>>>(Wout, bout, out);
}